// round 1
// baseline (speedup 1.0000x reference)
#include <cuda_runtime.h>
#include <math.h>

#define SS 512
#define PP 64
#define TT 8
#define NN (SS*PP)            // 32768

#define ENC_ELEMS (NN*72)     // 2359296
#define SEQ_ELEMS (TT*NN*32)  // 8388608

// Scratch (static __device__ arrays — no allocation at runtime)
__device__ float g_graph_in[SEQ_ELEMS];        // 32 MB: GAT output -> graph LSTM input
__device__ float g_x2[(size_t)SS*TT*64*64];    // 64 MB: GAT layer0 output (elu'd)
__device__ float g_traj_fb[SEQ_ELEMS];         // fallback if out only holds encoded
__device__ float g_graph_fb[SEQ_ELEMS];

__device__ __forceinline__ float sigf(float x){ return 1.0f/(1.0f+expf(-x)); }

// ---------------------------------------------------------------------------
// LSTM over T=8 steps, input dim 3, hidden 32. One warp per pedestrian,
// lane = hidden index. Whh stored transposed in smem: sWhhT[k*128+row],
// so lanes read consecutive addresses (conflict-free).
// ---------------------------------------------------------------------------
__global__ void lstm_traj_kernel(const float* __restrict__ x,
        const float* __restrict__ h0, const float* __restrict__ c0,
        const float* __restrict__ Wih, const float* __restrict__ Whh,
        const float* __restrict__ bih, const float* __restrict__ bhh,
        float* __restrict__ hs)
{
    __shared__ float sWih[384];     // [128][3]
    __shared__ float sWhhT[4096];   // [32][128] (k-major)
    __shared__ float sb[128];
    const int tid = threadIdx.x;
    for (int i = tid; i < 384; i += 256) sWih[i] = Wih[i];
    for (int i = tid; i < 4096; i += 256) { int row = i >> 5, k = i & 31; sWhhT[k*128 + row] = Whh[i]; }
    if (tid < 128) sb[tid] = bih[tid] + bhh[tid];
    __syncthreads();

    const int lane = tid & 31;
    const int n = blockIdx.x * 8 + (tid >> 5);
    float h = h0[n*32 + lane];
    float c = c0[n*32 + lane];

    #pragma unroll
    for (int t = 0; t < TT; t++) {
        const float* xp = x + ((size_t)t*NN + n) * 3;
        float x0 = xp[0], x1 = xp[1], x2 = xp[2];
        int r0 = lane, r1 = 32 + lane, r2 = 64 + lane, r3 = 96 + lane;
        float a0 = sb[r0] + sWih[r0*3]*x0 + sWih[r0*3+1]*x1 + sWih[r0*3+2]*x2;
        float a1 = sb[r1] + sWih[r1*3]*x0 + sWih[r1*3+1]*x1 + sWih[r1*3+2]*x2;
        float a2 = sb[r2] + sWih[r2*3]*x0 + sWih[r2*3+1]*x1 + sWih[r2*3+2]*x2;
        float a3 = sb[r3] + sWih[r3*3]*x0 + sWih[r3*3+1]*x1 + sWih[r3*3+2]*x2;
        #pragma unroll
        for (int k = 0; k < 32; k++) {
            float hk = __shfl_sync(0xffffffffu, h, k);
            const float* w = &sWhhT[k*128 + lane];
            a0 += w[0]  * hk;
            a1 += w[32] * hk;
            a2 += w[64] * hk;
            a3 += w[96] * hk;
        }
        c = sigf(a1) * c + sigf(a0) * tanhf(a2);
        h = sigf(a3) * tanhf(c);
        hs[((size_t)t*NN + n)*32 + lane] = h;
    }
}

// ---------------------------------------------------------------------------
// GAT layer 0: one block per (scene, timestep) graph. B=4096 blocks.
// x[64,32] -> instance-norm -> hp[64, 4*16] -> additive attention per head ->
// out + bias -> elu -> g_x2[b, 64, 64]
// ---------------------------------------------------------------------------
__global__ void gat0_kernel(const float* __restrict__ traj,
        const float* __restrict__ w0, const float* __restrict__ as0,
        const float* __restrict__ ad0, const float* __restrict__ b0)
{
    __shared__ float shp[4096];   // hp[p][h*16+o]
    __shared__ float sbuf[4096];  // w0, then attn-exp per head
    __shared__ float sx[2048];    // x[p][f]
    __shared__ float sS[256], sD[256];
    __shared__ float smean[32], sinv[32], srsum[64];
    const int tid = threadIdx.x;
    const int b = blockIdx.x, sIdx = b >> 3, tIdx = b & 7;

    for (int i = tid; i < 2048; i += 256) {
        int p = i >> 5, f = i & 31;
        sx[i] = traj[((size_t)tIdx*NN + sIdx*64 + p)*32 + f];
    }
    for (int i = tid; i < 2048; i += 256) sbuf[i] = w0[i];
    __syncthreads();

    // instance norm over p per feature f
    if (tid < 32) {
        float s = 0.f, s2 = 0.f;
        for (int p = 0; p < 64; p++) { float v = sx[p*32 + tid]; s += v; s2 += v*v; }
        float m = s * (1.0f/64.0f);
        float var = s2 * (1.0f/64.0f) - m*m;
        smean[tid] = m; sinv[tid] = rsqrtf(var + 1e-5f);
    }
    __syncthreads();
    for (int i = tid; i < 2048; i += 256) { int f = i & 31; sx[i] = (sx[i] - smean[f]) * sinv[f]; }
    __syncthreads();

    // hp[p][h*16+o] = sum_f x[p][f] * w0[h][f][o]
    for (int i = tid; i < 4096; i += 256) {
        int p = i >> 6, j = i & 63, hh = j >> 4, o = j & 15;
        const float* wp = &sbuf[hh*512 + o];
        const float* xp = &sx[p*32];
        float acc = 0.f;
        #pragma unroll
        for (int f = 0; f < 32; f++) acc += xp[f] * wp[f*16];
        shp[i] = acc;
    }
    __syncthreads();

    // s[h][p], d[h][p]
    {
        int hh = tid >> 6, p = tid & 63;
        const float* hpp = &shp[p*64 + hh*16];
        float as = 0.f, ad = 0.f;
        #pragma unroll
        for (int o = 0; o < 16; o++) { float v = hpp[o]; as += v * as0[hh*16+o]; ad += v * ad0[hh*16+o]; }
        sS[tid] = as; sD[tid] = ad;
    }
    __syncthreads();

    for (int hh = 0; hh < 4; hh++) {
        if (tid < 64) {  // one thread per row p: softmax(exp) into sbuf
            int p = tid; float sp = sS[hh*64 + p];
            float mx = -1e30f;
            for (int m = 0; m < 64; m++) { float l = sp + sD[hh*64+m]; l = (l > 0.f) ? l : 0.2f*l; mx = fmaxf(mx, l); }
            float sum = 0.f;
            for (int m = 0; m < 64; m++) {
                float l = sp + sD[hh*64+m]; l = (l > 0.f) ? l : 0.2f*l;
                float e = expf(l - mx); sbuf[p*64 + m] = e; sum += e;
            }
            srsum[p] = sum;
        }
        __syncthreads();
        for (int i = tid; i < 1024; i += 256) {
            int p = i >> 4, o = i & 15;
            const float* ap = &sbuf[p*64];
            float acc = 0.f;
            #pragma unroll
            for (int m = 0; m < 64; m++) acc += ap[m] * shp[m*64 + hh*16 + o];
            float v = acc / srsum[p] + b0[o];
            v = (v > 0.f) ? v : expm1f(v);  // elu
            g_x2[((size_t)b*64 + p)*64 + hh*16 + o] = v;
        }
        __syncthreads();
    }
}

// ---------------------------------------------------------------------------
// GAT layer 1: x2[64,64] -> instance-norm -> hp[64,32] -> 1-head attention ->
// out + bias -> g_graph_in[t, s*64+p, 32]
// ---------------------------------------------------------------------------
__global__ void gat1_kernel(const float* __restrict__ w1, const float* __restrict__ as1,
        const float* __restrict__ ad1, const float* __restrict__ b1)
{
    __shared__ float sx[4096];
    __shared__ float shp[2048];
    __shared__ float sbuf[4096];  // w1, then attn-exp
    __shared__ float sS[64], sD[64], smean[64], sinv[64], srsum[64];
    const int tid = threadIdx.x;
    const int b = blockIdx.x, sIdx = b >> 3, tIdx = b & 7;

    for (int i = tid; i < 4096; i += 256) sx[i] = g_x2[(size_t)b*4096 + i];
    __syncthreads();

    if (tid < 64) {
        float s = 0.f, s2 = 0.f;
        for (int p = 0; p < 64; p++) { float v = sx[p*64 + tid]; s += v; s2 += v*v; }
        float m = s * (1.0f/64.0f);
        float var = s2 * (1.0f/64.0f) - m*m;
        smean[tid] = m; sinv[tid] = rsqrtf(var + 1e-5f);
    }
    __syncthreads();
    for (int i = tid; i < 4096; i += 256) { int f = i & 63; sx[i] = (sx[i] - smean[f]) * sinv[f]; }
    for (int i = tid; i < 2048; i += 256) sbuf[i] = w1[i];
    __syncthreads();

    for (int i = tid; i < 2048; i += 256) {
        int p = i >> 5, o = i & 31;
        const float* xp = &sx[p*64];
        const float* wp = &sbuf[o];
        float acc = 0.f;
        #pragma unroll
        for (int f = 0; f < 64; f++) acc += xp[f] * wp[f*32];
        shp[i] = acc;
    }
    __syncthreads();

    if (tid < 64) {
        int p = tid; const float* hpp = &shp[p*32];
        float as = 0.f, ad = 0.f;
        #pragma unroll
        for (int o = 0; o < 32; o++) { float v = hpp[o]; as += v * as1[o]; ad += v * ad1[o]; }
        sS[p] = as; sD[p] = ad;
    }
    __syncthreads();

    if (tid < 64) {
        int p = tid; float sp = sS[p];
        float mx = -1e30f;
        for (int m = 0; m < 64; m++) { float l = sp + sD[m]; l = (l > 0.f) ? l : 0.2f*l; mx = fmaxf(mx, l); }
        float sum = 0.f;
        for (int m = 0; m < 64; m++) {
            float l = sp + sD[m]; l = (l > 0.f) ? l : 0.2f*l;
            float e = expf(l - mx); sbuf[p*64 + m] = e; sum += e;
        }
        srsum[p] = sum;
    }
    __syncthreads();

    for (int i = tid; i < 2048; i += 256) {
        int p = i >> 5, o = i & 31;
        const float* ap = &sbuf[p*64];
        float acc = 0.f;
        #pragma unroll
        for (int m = 0; m < 64; m++) acc += ap[m] * shp[m*32 + o];
        float v = acc / srsum[p] + b1[o];
        g_graph_in[((size_t)tIdx*NN + sIdx*64 + p)*32 + o] = v;
    }
}

// ---------------------------------------------------------------------------
// LSTM over T=8 steps, input dim 32 (from g_graph_in), hidden 32.
// ---------------------------------------------------------------------------
__global__ void lstm_graph_kernel(
        const float* __restrict__ h0, const float* __restrict__ c0,
        const float* __restrict__ Wih, const float* __restrict__ Whh,
        const float* __restrict__ bih, const float* __restrict__ bhh,
        float* __restrict__ hs)
{
    __shared__ float sWihT[4096];
    __shared__ float sWhhT[4096];
    __shared__ float sb[128];
    const int tid = threadIdx.x;
    for (int i = tid; i < 4096; i += 256) {
        int row = i >> 5, k = i & 31;
        sWihT[k*128 + row] = Wih[i];
        sWhhT[k*128 + row] = Whh[i];
    }
    if (tid < 128) sb[tid] = bih[tid] + bhh[tid];
    __syncthreads();

    const int lane = tid & 31;
    const int n = blockIdx.x * 8 + (tid >> 5);
    float h = h0[n*32 + lane];
    float c = c0[n*32 + lane];

    for (int t = 0; t < TT; t++) {
        float xv = g_graph_in[((size_t)t*NN + n)*32 + lane];
        float a0 = sb[lane], a1 = sb[32+lane], a2 = sb[64+lane], a3 = sb[96+lane];
        #pragma unroll
        for (int k = 0; k < 32; k++) {
            float xk = __shfl_sync(0xffffffffu, xv, k);
            float hk = __shfl_sync(0xffffffffu, h,  k);
            const float* wi = &sWihT[k*128 + lane];
            const float* wh = &sWhhT[k*128 + lane];
            a0 += wi[0]  * xk + wh[0]  * hk;
            a1 += wi[32] * xk + wh[32] * hk;
            a2 += wi[64] * xk + wh[64] * hk;
            a3 += wi[96] * xk + wh[96] * hk;
        }
        c = sigf(a1) * c + sigf(a0) * tanhf(a2);
        h = sigf(a3) * tanhf(c);
        hs[((size_t)t*NN + n)*32 + lane] = h;
    }
}

// ---------------------------------------------------------------------------
// encoded[n, 0:32]=traj_hs[7,n], [32:64]=graph_hs[7,n], [64:72]=z[n/64]
// ---------------------------------------------------------------------------
__global__ void concat_kernel(const float* __restrict__ z,
        const float* __restrict__ traj, const float* __restrict__ graph,
        float* __restrict__ out)
{
    int idx = blockIdx.x * blockDim.x + threadIdx.x;
    if (idx >= NN*72) return;
    int n = idx / 72, j = idx - n*72;
    float v;
    if (j < 32)      v = traj [((size_t)7*NN + n)*32 + j];
    else if (j < 64) v = graph[((size_t)7*NN + n)*32 + (j - 32)];
    else             v = z[(n >> 6)*8 + (j - 64)];
    out[idx] = v;
}

extern "C" void kernel_launch(void* const* d_in, const int* in_sizes, int n_in,
                              void* d_out, int out_size) {
    const float* obs  = (const float*)d_in[0];
    const float* h0t  = (const float*)d_in[1];
    const float* c0t  = (const float*)d_in[2];
    const float* h0g  = (const float*)d_in[3];
    const float* c0g  = (const float*)d_in[4];
    const float* z    = (const float*)d_in[5];
    const float* WihT = (const float*)d_in[6];
    const float* WhhT = (const float*)d_in[7];
    const float* bihT = (const float*)d_in[8];
    const float* bhhT = (const float*)d_in[9];
    const float* WihG = (const float*)d_in[10];
    const float* WhhG = (const float*)d_in[11];
    const float* bihG = (const float*)d_in[12];
    const float* bhhG = (const float*)d_in[13];
    const float* w0   = (const float*)d_in[14];
    const float* as0  = (const float*)d_in[15];
    const float* ad0  = (const float*)d_in[16];
    const float* b0   = (const float*)d_in[17];
    const float* w1   = (const float*)d_in[18];
    const float* as1  = (const float*)d_in[19];
    const float* ad1  = (const float*)d_in[20];
    const float* b1   = (const float*)d_in[21];
    float* out = (float*)d_out;

    // Output layout assumption: [encoded | graph_hs | traj_hs] flattened.
    float* traj_hs;
    float* graph_hs;
    if (out_size >= ENC_ELEMS + 2*SEQ_ELEMS) {
        graph_hs = out + ENC_ELEMS;
        traj_hs  = out + ENC_ELEMS + SEQ_ELEMS;
    } else {
        // fallback: only encoded in d_out; sequences go to device scratch
        void* pt = nullptr; void* pg = nullptr;
        cudaGetSymbolAddress(&pt, g_traj_fb);
        cudaGetSymbolAddress(&pg, g_graph_fb);
        traj_hs  = (float*)pt;
        graph_hs = (float*)pg;
    }

    lstm_traj_kernel<<<NN/8, 256>>>(obs, h0t, c0t, WihT, WhhT, bihT, bhhT, traj_hs);
    gat0_kernel<<<SS*TT, 256>>>(traj_hs, w0, as0, ad0, b0);
    gat1_kernel<<<SS*TT, 256>>>(w1, as1, ad1, b1);
    lstm_graph_kernel<<<NN/8, 256>>>(h0g, c0g, WihG, WhhG, bihG, bhhG, graph_hs);
    concat_kernel<<<(NN*72 + 255)/256, 256>>>(z, traj_hs, graph_hs, out);
}